// round 6
// baseline (speedup 1.0000x reference)
#include <cuda_runtime.h>
#include <stdint.h>

#define NBINS    4096
#define CAND_CAP 2048
#define MAXN     524288
#define KSEL     64
#define TPB      256
#define SGRID    1036   // 7 CTAs/SM x 148 SMs

// Scratch (__device__ globals; zero at module load). Per-replay reset:
// g_count by k_score block0 at start (only touched later by k_compact);
// g_ticket by k_score's last block; g_hist by k_select blocks 64-79.
__device__ uint32_t            g_keys[MAXN];
__device__ uint32_t            g_hist[NBINS];
__device__ int                 g_count;
__device__ int                 g_ticket;
__device__ int                 g_B;
__device__ unsigned long long  g_cand[CAND_CAP];

__device__ __forceinline__ uint32_t f2key(float f) {
    uint32_t u = __float_as_uint(f);
    return (u & 0x80000000u) ? ~u : (u | 0x80000000u);
}
__device__ __forceinline__ float dot4(float4 a, float4 b) {
    return a.x*b.x + a.y*b.y + a.z*b.z + a.w*b.w;
}

// K1: 4 rows / warp iteration (8 independent LDG.128 in flight), 6-shuffle
// merged reduction, fused smem histogram. Last block to finish the global
// hist merge computes the threshold bin B (overlapped with kernel drain).
__global__ void k_score(const float4* __restrict__ q,
                        const float4* __restrict__ mat, int N) {
    __shared__ uint32_t sh[NBINS];
    __shared__ bool isLast;
    if (blockIdx.x == 0 && threadIdx.x == 0) g_count = 0;   // replay reset
    for (int i = threadIdx.x; i < NBINS; i += TPB) sh[i] = 0u;
    __syncthreads();

    const int lane   = threadIdx.x & 31;
    const int warp   = (blockIdx.x * TPB + threadIdx.x) >> 5;
    const int nwarps = (SGRID * TPB) >> 5;

    const float4 qa = q[lane];
    const float4 qb = q[lane + 32];

    for (int r0 = warp * 4; r0 < N; r0 += nwarps * 4) {
        const float4* p = mat + (size_t)r0 * 64;
        if (r0 + 3 < N) {
            float4 a0 = p[lane],       b0 = p[lane + 32];
            float4 a1 = p[lane + 64],  b1 = p[lane + 96];
            float4 a2 = p[lane + 128], b2 = p[lane + 160];
            float4 a3 = p[lane + 192], b3 = p[lane + 224];
            float s0 = dot4(a0, qa) + dot4(b0, qb);
            float s1 = dot4(a1, qa) + dot4(b1, qb);
            float s2 = dot4(a2, qa) + dot4(b2, qb);
            float s3 = dot4(a3, qa) + dot4(b3, qb);
            // Merged 4-value butterfly: 6 shuffles instead of 20.
            // After it, lane r (r<4) holds the full 32-lane sum of s_r.
            float u0 = (lane & 1) ? s1 : s0;
            float v0 = (lane & 1) ? s0 : s1;
            u0 += __shfl_xor_sync(0xffffffffu, v0, 1);
            float u1 = (lane & 1) ? s3 : s2;
            float v1 = (lane & 1) ? s2 : s3;
            u1 += __shfl_xor_sync(0xffffffffu, v1, 1);
            float w = (lane & 2) ? u1 : u0;
            float x = (lane & 2) ? u0 : u1;
            w += __shfl_xor_sync(0xffffffffu, x, 2);
            w += __shfl_xor_sync(0xffffffffu, w, 4);
            w += __shfl_xor_sync(0xffffffffu, w, 8);
            w += __shfl_xor_sync(0xffffffffu, w, 16);
            if (lane < 4) {
                uint32_t key = f2key(w);
                g_keys[r0 + lane] = key;
                atomicAdd(&sh[key >> 20], 1u);
            }
        } else {
            for (int r = r0; r < N; r++) {
                const float4* row = mat + (size_t)r * 64;
                float s = dot4(row[lane], qa) + dot4(row[lane + 32], qb);
                #pragma unroll
                for (int o = 16; o; o >>= 1) s += __shfl_xor_sync(0xffffffffu, s, o);
                if (lane == 0) {
                    uint32_t key = f2key(s);
                    g_keys[r] = key;
                    atomicAdd(&sh[key >> 20], 1u);
                }
            }
        }
    }
    __syncthreads();
    for (int i = threadIdx.x; i < NBINS; i += TPB) {
        uint32_t c = sh[i];
        if (c) atomicAdd(&g_hist[i], c);
    }

    // Last finishing block computes the threshold bin.
    __threadfence();
    if (threadIdx.x == 0)
        isLast = (atomicAdd(&g_ticket, 1) == SGRID - 1);
    __syncthreads();
    if (isLast) {
        __shared__ uint32_t part[TPB];
        // Each thread sums 16 hist entries (L2 reads via __ldcg; atomics
        // updated at L2, so bypass L1).
        uint32_t s = 0;
        #pragma unroll 16
        for (int j = 0; j < 16; j++)
            s += __ldcg(&g_hist[threadIdx.x * 16 + j]);
        part[threadIdx.x] = s;
        __syncthreads();
        if (threadIdx.x == 0) {
            long long cum = 0;
            int seg = 0;
            for (int i = TPB - 1; i >= 0; i--) {
                cum += part[i];
                if (cum >= KSEL) { seg = i; break; }
            }
            long long c2 = cum - part[seg];
            int B = seg * 16;
            for (int b = seg * 16 + 15; b >= seg * 16; b--) {
                c2 += __ldcg(&g_hist[b]);
                if (c2 >= KSEL) { B = b; break; }
            }
            g_B = B;
            g_ticket = 0;          // reset for next replay
        }
    }
}

// K2: compact candidates (key bin >= g_B), exactly one uint4 per thread.
// Packed key = (key32<<32) | ~idx : higher score first; ties -> smaller idx.
__global__ void k_compact(int N4) {
    const int B = g_B;
    int i = blockIdx.x * TPB + threadIdx.x;
    if (i >= N4) return;
    uint4 k4 = ((const uint4*)g_keys)[i];
    uint32_t base = (uint32_t)i * 4u;
    #pragma unroll
    for (int j = 0; j < 4; j++) {
        uint32_t key = (j == 0) ? k4.x : (j == 1) ? k4.y : (j == 2) ? k4.z : k4.w;
        if ((int)(key >> 20) >= B) {
            int p = atomicAdd(&g_count, 1);
            if (p < CAND_CAP)
                g_cand[p] = ((unsigned long long)key << 32)
                          | (uint32_t)(~(base + (uint32_t)j));
        }
    }
}

// K3: blocks 0-63: redundant rank computation (packed keys unique -> unique
// ranks; rank<64 selects) + gather ONE output row each. Block 0 also writes
// the index vector. Blocks 64-79: zero g_hist for the next replay.
__global__ void k_select(const float4* __restrict__ mat,
                         float* __restrict__ out, int out_size) {
    if (blockIdx.x >= KSEL) {
        int idx = (blockIdx.x - KSEL) * TPB + threadIdx.x;
        g_hist[idx] = 0u;
        return;
    }

    __shared__ unsigned long long cv[CAND_CAP];
    __shared__ uint32_t rows[KSEL];
    const int tid = threadIdx.x;

    int C = g_count;
    if (C > CAND_CAP) C = CAND_CAP;

    for (int j = tid; j < C; j += TPB) cv[j] = g_cand[j];
    __syncthreads();
    for (int j = tid; j < C; j += TPB) {
        unsigned long long v = cv[j];
        int rank = 0;
        for (int i = 0; i < C; i++) rank += (cv[i] > v);
        if (rank < KSEL) rows[rank] = ~(uint32_t)(v & 0xFFFFFFFFull);
    }
    __syncthreads();

    const int r = blockIdx.x;
    float4* out4 = (float4*)out;
    if (tid < 64)
        out4[r * 64 + tid] = mat[(size_t)rows[r] * 64 + tid];
    if (r == 0 && tid < KSEL && out_size >= KSEL * 256 + KSEL)
        out[KSEL * 256 + tid] = (float)rows[tid];
}

extern "C" void kernel_launch(void* const* d_in, const int* in_sizes, int n_in,
                              void* d_out, int out_size) {
    const float* q   = (const float*)d_in[0];   // [256]
    const float* mat = (const float*)d_in[1];   // [500000, 256]
    int D = in_sizes[0];
    int N = in_sizes[1] / D;
    int N4 = N / 4;

    k_score<<<SGRID, TPB>>>((const float4*)q, (const float4*)mat, N);
    k_compact<<<(N4 + TPB - 1) / TPB, TPB>>>(N4);
    k_select<<<KSEL + NBINS / TPB, TPB>>>((const float4*)mat, (float*)d_out, out_size);
}

// round 7
// speedup vs baseline: 1.1029x; 1.1029x over previous
#include <cuda_runtime.h>
#include <stdint.h>

#define NBINS    4096
#define CAND_CAP 2048
#define MAXN     524288
#define KSEL     64
#define TPB      256
#define SGRID    592    // 4 CTAs/SM x 148 SMs — proven-fastest for k_score

// Scratch (__device__ globals; zero at module load). Per-replay reset:
// g_count by k_score block0 at start (only touched later by k_compact);
// g_ticket by k_score's last block; g_hist by k_select blocks 64-79.
__device__ uint32_t            g_keys[MAXN];
__device__ uint32_t            g_hist[NBINS];
__device__ int                 g_count;
__device__ int                 g_ticket;
__device__ int                 g_B;
__device__ unsigned long long  g_cand[CAND_CAP];

__device__ __forceinline__ uint32_t f2key(float f) {
    uint32_t u = __float_as_uint(f);
    return (u & 0x80000000u) ? ~u : (u | 0x80000000u);
}
__device__ __forceinline__ float dot4(float4 a, float4 b) {
    return a.x*b.x + a.y*b.y + a.z*b.z + a.w*b.w;
}

// K1: EXACT R3 score loop (4 rows/warp iter, 8 independent LDG.128 in
// flight, plain xor-shuffle reductions, fused smem histogram) — measured
// 83.2us @ 6.23TB/s. Appended: last-finishing block computes threshold
// bin B during kernel drain (saves a launch + serial scan later).
__global__ void k_score(const float4* __restrict__ q,
                        const float4* __restrict__ mat, int N) {
    __shared__ uint32_t sh[NBINS];
    __shared__ bool isLast;
    if (blockIdx.x == 0 && threadIdx.x == 0) g_count = 0;   // replay reset
    for (int i = threadIdx.x; i < NBINS; i += TPB) sh[i] = 0u;
    __syncthreads();

    const int lane   = threadIdx.x & 31;
    const int warp   = (blockIdx.x * TPB + threadIdx.x) >> 5;
    const int nwarps = (SGRID * TPB) >> 5;

    const float4 qa = q[lane];
    const float4 qb = q[lane + 32];

    for (int r0 = warp * 4; r0 < N; r0 += nwarps * 4) {
        const float4* p = mat + (size_t)r0 * 64;
        if (r0 + 3 < N) {
            float4 a0 = p[lane],       b0 = p[lane + 32];
            float4 a1 = p[lane + 64],  b1 = p[lane + 96];
            float4 a2 = p[lane + 128], b2 = p[lane + 160];
            float4 a3 = p[lane + 192], b3 = p[lane + 224];
            float s0 = dot4(a0, qa) + dot4(b0, qb);
            float s1 = dot4(a1, qa) + dot4(b1, qb);
            float s2 = dot4(a2, qa) + dot4(b2, qb);
            float s3 = dot4(a3, qa) + dot4(b3, qb);
            #pragma unroll
            for (int o = 16; o; o >>= 1) {
                s0 += __shfl_xor_sync(0xffffffffu, s0, o);
                s1 += __shfl_xor_sync(0xffffffffu, s1, o);
                s2 += __shfl_xor_sync(0xffffffffu, s2, o);
                s3 += __shfl_xor_sync(0xffffffffu, s3, o);
            }
            if (lane < 4) {
                float s = (lane == 0) ? s0 : (lane == 1) ? s1 : (lane == 2) ? s2 : s3;
                uint32_t key = f2key(s);
                g_keys[r0 + lane] = key;
                atomicAdd(&sh[key >> 20], 1u);
            }
        } else {
            for (int r = r0; r < N; r++) {
                const float4* row = mat + (size_t)r * 64;
                float s = dot4(row[lane], qa) + dot4(row[lane + 32], qb);
                #pragma unroll
                for (int o = 16; o; o >>= 1) s += __shfl_xor_sync(0xffffffffu, s, o);
                if (lane == 0) {
                    uint32_t key = f2key(s);
                    g_keys[r] = key;
                    atomicAdd(&sh[key >> 20], 1u);
                }
            }
        }
    }
    __syncthreads();
    for (int i = threadIdx.x; i < NBINS; i += TPB) {
        uint32_t c = sh[i];
        if (c) atomicAdd(&g_hist[i], c);
    }

    // Last finishing block computes the threshold bin (overlaps drain).
    __threadfence();
    if (threadIdx.x == 0)
        isLast = (atomicAdd(&g_ticket, 1) == SGRID - 1);
    __syncthreads();
    if (isLast) {
        __shared__ uint32_t part[TPB];
        uint32_t s = 0;
        #pragma unroll 16
        for (int j = 0; j < 16; j++)
            s += __ldcg(&g_hist[threadIdx.x * 16 + j]);
        part[threadIdx.x] = s;
        __syncthreads();
        if (threadIdx.x == 0) {
            long long cum = 0;
            int seg = 0;
            for (int i = TPB - 1; i >= 0; i--) {
                cum += part[i];
                if (cum >= KSEL) { seg = i; break; }
            }
            long long c2 = cum - part[seg];
            int B = seg * 16;
            for (int b = seg * 16 + 15; b >= seg * 16; b--) {
                c2 += __ldcg(&g_hist[b]);
                if (c2 >= KSEL) { B = b; break; }
            }
            g_B = B;
            g_ticket = 0;          // reset for next replay
        }
    }
}

// K2: compact candidates (key bin >= g_B), exactly one uint4 per thread.
// Packed key = (key32<<32) | ~idx : higher score first; ties -> smaller idx.
__global__ void k_compact(int N4) {
    const int B = g_B;
    int i = blockIdx.x * TPB + threadIdx.x;
    if (i >= N4) return;
    uint4 k4 = ((const uint4*)g_keys)[i];
    uint32_t base = (uint32_t)i * 4u;
    #pragma unroll
    for (int j = 0; j < 4; j++) {
        uint32_t key = (j == 0) ? k4.x : (j == 1) ? k4.y : (j == 2) ? k4.z : k4.w;
        if ((int)(key >> 20) >= B) {
            int p = atomicAdd(&g_count, 1);
            if (p < CAND_CAP)
                g_cand[p] = ((unsigned long long)key << 32)
                          | (uint32_t)(~(base + (uint32_t)j));
        }
    }
}

// K3: blocks 0-63: redundant rank computation (packed keys unique -> unique
// ranks; rank<64 selects) + gather ONE output row each. Block 0 also writes
// the index vector. Blocks 64-79: zero g_hist for the next replay.
__global__ void k_select(const float4* __restrict__ mat,
                         float* __restrict__ out, int out_size) {
    if (blockIdx.x >= KSEL) {
        int idx = (blockIdx.x - KSEL) * TPB + threadIdx.x;
        g_hist[idx] = 0u;
        return;
    }

    __shared__ unsigned long long cv[CAND_CAP];
    __shared__ uint32_t rows[KSEL];
    const int tid = threadIdx.x;

    int C = g_count;
    if (C > CAND_CAP) C = CAND_CAP;

    for (int j = tid; j < C; j += TPB) cv[j] = g_cand[j];
    __syncthreads();
    for (int j = tid; j < C; j += TPB) {
        unsigned long long v = cv[j];
        int rank = 0;
        for (int i = 0; i < C; i++) rank += (cv[i] > v);
        if (rank < KSEL) rows[rank] = ~(uint32_t)(v & 0xFFFFFFFFull);
    }
    __syncthreads();

    const int r = blockIdx.x;
    float4* out4 = (float4*)out;
    if (tid < 64)
        out4[r * 64 + tid] = mat[(size_t)rows[r] * 64 + tid];
    if (r == 0 && tid < KSEL && out_size >= KSEL * 256 + KSEL)
        out[KSEL * 256 + tid] = (float)rows[tid];
}

extern "C" void kernel_launch(void* const* d_in, const int* in_sizes, int n_in,
                              void* d_out, int out_size) {
    const float* q   = (const float*)d_in[0];   // [256]
    const float* mat = (const float*)d_in[1];   // [500000, 256]
    int D = in_sizes[0];
    int N = in_sizes[1] / D;
    int N4 = N / 4;

    k_score<<<SGRID, TPB>>>((const float4*)q, (const float4*)mat, N);
    k_compact<<<(N4 + TPB - 1) / TPB, TPB>>>(N4);
    k_select<<<KSEL + NBINS / TPB, TPB>>>((const float4*)mat, (float*)d_out, out_size);
}